// round 10
// baseline (speedup 1.0000x reference)
#include <cuda_runtime.h>
#include <cuda_bf16.h>
#include <mma.h>
#include <math.h>

using namespace nvcuda;

typedef unsigned long long ull;
typedef unsigned int u32;

#define Cc 128
#define Hd 128
#define Wd 128
#define HWs 16384
#define BT 16
#define NBm 2

// ---------------- device scratch ----------------
__device__ float g_qw[(size_t)2 * 8388608];   // scales 0,1 fp32
__device__ float g_kw[(size_t)2 * 8388608];
__device__ float g_vw[(size_t)2 * 8388608];
__device__ float g_ow[(size_t)4 * 8388608];
__device__ float g_c1[(size_t)3 * 16 * 16384 * 128];   // conv1 dense out
__device__ float g_part[(size_t)1 << 24];
__device__ float g_attn[(size_t)NBm * 512 * 512];
__device__ __nv_bfloat16 g_ath[(size_t)NBm * 512 * 512];
__device__ __nv_bfloat16 g_atl[(size_t)NBm * 512 * 512];
__device__ __nv_bfloat16 g_qh[(size_t)2 * 8388608];   // scales 2,3 bf16 hi/lo
__device__ __nv_bfloat16 g_ql[(size_t)2 * 8388608];
__device__ __nv_bfloat16 g_kh[(size_t)2 * 8388608];
__device__ __nv_bfloat16 g_kl[(size_t)2 * 8388608];
__device__ __nv_bfloat16 g_vh[(size_t)2 * 8388608];
__device__ __nv_bfloat16 g_vl[(size_t)2 * 8388608];
__device__ __nv_bfloat16 g_xh[(size_t)33554432];
__device__ __nv_bfloat16 g_xl[(size_t)33554432];
__device__ __nv_bfloat16 g_ah[(size_t)33554432];
__device__ __nv_bfloat16 g_al[(size_t)33554432];
__device__ __nv_bfloat16 g_w3h[9 * 128 * 128];
__device__ __nv_bfloat16 g_w3l[9 * 128 * 128];
__device__ __nv_bfloat16 g_w1h[3 * 128 * 128];
__device__ __nv_bfloat16 g_w1l[3 * 128 * 128];

// ---------------- helpers ----------------
__device__ __forceinline__ void ffma2(ull& d, ull a, ull b) {
    asm("fma.rn.f32x2 %0, %1, %2, %0;" : "+l"(d) : "l"(a), "l"(b));
}
__device__ __forceinline__ float hsum2(ull v) {
    float2 f = *reinterpret_cast<float2*>(&v);
    return f.x + f.y;
}
__device__ __forceinline__ ull pack2(float a) {
    ull r; asm("mov.b64 %0,{%1,%1};" : "=l"(r) : "f"(a)); return r;
}
__device__ __forceinline__ void bsplit(float v, __nv_bfloat16& h, __nv_bfloat16& l) {
    h = __float2bfloat16(v);
    l = __float2bfloat16(v - __bfloat162float(h));
}
__device__ __forceinline__ u32 smem_u32(const void* p) {
    u32 a; asm("{ .reg .u64 t; cvta.to.shared.u64 t, %1; cvt.u32.u64 %0, t; }"
               : "=r"(a) : "l"(p));
    return a;
}
__device__ __forceinline__ void cpa16(u32 dst, const void* src) {
    asm volatile("cp.async.cg.shared.global [%0], [%1], 16;"
                 :: "r"(dst), "l"(src) : "memory");
}
#define CP_COMMIT() asm volatile("cp.async.commit_group;" ::: "memory")
#define CP_WAIT(n)  asm volatile("cp.async.wait_group %0;" :: "n"(n) : "memory")

typedef wmma::fragment<wmma::matrix_a, 16, 16, 16, __nv_bfloat16, wmma::row_major> FragA;
typedef wmma::fragment<wmma::matrix_b, 16, 16, 16, __nv_bfloat16, wmma::col_major> FragB;
typedef wmma::fragment<wmma::matrix_b, 16, 16, 16, __nv_bfloat16, wmma::row_major> FragBr;
typedef wmma::fragment<wmma::accumulator, 16, 16, 16, float> FragC;

// 3-product hi/lo microkernel: warp tile 32x64, K=128, ldm 136.
template<bool BROW, class FB>
__device__ __forceinline__ void mma3(const __nv_bfloat16* pAh, const __nv_bfloat16* pAl,
                                     const __nv_bfloat16* pBh, const __nv_bfloat16* pBl,
                                     FragC (&acc)[2][4])
{
#pragma unroll
    for (int kt = 0; kt < 8; kt++) {
        int k0 = kt * 16;
        FragA ah[2], al[2];
        FB bh[4], bl[4];
#pragma unroll
        for (int i = 0; i < 2; i++) {
            wmma::load_matrix_sync(ah[i], pAh + (16 * i) * 136 + k0, 136);
            wmma::load_matrix_sync(al[i], pAl + (16 * i) * 136 + k0, 136);
        }
#pragma unroll
        for (int j = 0; j < 4; j++) {
            int o = BROW ? (k0 * 136 + 16 * j) : ((16 * j) * 136 + k0);
            wmma::load_matrix_sync(bh[j], pBh + o, 136);
            wmma::load_matrix_sync(bl[j], pBl + o, 136);
        }
#pragma unroll
        for (int i = 0; i < 2; i++)
#pragma unroll
            for (int j = 0; j < 4; j++) {
                wmma::mma_sync(acc[i][j], ah[i], bh[j], acc[i][j]);
                wmma::mma_sync(acc[i][j], ah[i], bl[j], acc[i][j]);
                wmma::mma_sync(acc[i][j], al[i], bh[j], acc[i][j]);
            }
    }
}

// chunk microkernels: B is one bf16 term (hi or lo), 64 oc rows, k-major.
__device__ __forceinline__ void mma_bh(const __nv_bfloat16* pAh, const __nv_bfloat16* pAl,
                                       const __nv_bfloat16* pB, FragC (&acc)[2][4])
{
#pragma unroll
    for (int kt = 0; kt < 8; kt++) {
        int k0 = kt * 16;
        FragA ah[2], al[2];
        FragB b[4];
#pragma unroll
        for (int i = 0; i < 2; i++) {
            wmma::load_matrix_sync(ah[i], pAh + (16 * i) * 136 + k0, 136);
            wmma::load_matrix_sync(al[i], pAl + (16 * i) * 136 + k0, 136);
        }
#pragma unroll
        for (int j = 0; j < 4; j++)
            wmma::load_matrix_sync(b[j], pB + (16 * j) * 136 + k0, 136);
#pragma unroll
        for (int i = 0; i < 2; i++)
#pragma unroll
            for (int j = 0; j < 4; j++) {
                wmma::mma_sync(acc[i][j], ah[i], b[j], acc[i][j]);
                wmma::mma_sync(acc[i][j], al[i], b[j], acc[i][j]);
            }
    }
}
__device__ __forceinline__ void mma_bl(const __nv_bfloat16* pAh,
                                       const __nv_bfloat16* pB, FragC (&acc)[2][4])
{
#pragma unroll
    for (int kt = 0; kt < 8; kt++) {
        int k0 = kt * 16;
        FragA ah[2];
        FragB b[4];
#pragma unroll
        for (int i = 0; i < 2; i++)
            wmma::load_matrix_sync(ah[i], pAh + (16 * i) * 136 + k0, 136);
#pragma unroll
        for (int j = 0; j < 4; j++)
            wmma::load_matrix_sync(b[j], pB + (16 * j) * 136 + k0, 136);
#pragma unroll
        for (int i = 0; i < 2; i++)
#pragma unroll
            for (int j = 0; j < 4; j++)
                wmma::mma_sync(acc[i][j], ah[i], b[j], acc[i][j]);
    }
}

// ============ prep: x -> channel-last bf16 hi/lo ============
__global__ __launch_bounds__(256)
void prep_x_kernel(const float* __restrict__ x)
{
    __shared__ float sb[64][130];
    int y = blockIdx.x, img = blockIdx.y, tid = threadIdx.x;
    for (int ch = 0; ch < 2; ch++) {
        for (int idx = tid; idx < 64 * 128; idx += 256) {
            int cl = idx >> 7, xp = idx & 127;
            sb[cl][xp] = x[((size_t)img * 128 + ch * 64 + cl) * HWs + y * 128 + xp];
        }
        __syncthreads();
        for (int idx = tid; idx < 64 * 128; idx += 256) {
            int px = idx >> 6, cl = idx & 63;
            __nv_bfloat16 h, l;
            bsplit(sb[cl][px], h, l);
            size_t o = (((size_t)img * 128 + y) * 128 + px) * 128 + ch * 64 + cl;
            g_xh[o] = h; g_xl[o] = l;
        }
        __syncthreads();
    }
}

// ============ prep: weights ============
__global__ void prep_w3_kernel(const float* __restrict__ wo)
{
    int i = blockIdx.x * 256 + threadIdx.x;
    if (i >= 9 * 128 * 128) return;
    int tap = i / 16384, r = i % 16384, oc = r >> 7, ic = r & 127;
    __nv_bfloat16 h, l;
    bsplit(wo[((size_t)oc * 128 + ic) * 9 + tap], h, l);
    size_t o = ((size_t)tap * 128 + oc) * 128 + ic;
    g_w3h[o] = h; g_w3l[o] = l;
}
__global__ void prep_w1_kernel(const float* __restrict__ wq,
                               const float* __restrict__ wk,
                               const float* __restrict__ wv)
{
    int i = blockIdx.x * 256 + threadIdx.x;
    if (i >= 3 * 16384) return;
    int o = i / 16384, r = i % 16384;
    const float* w = (o == 0) ? wq : (o == 1) ? wk : wv;
    __nv_bfloat16 h, l;
    bsplit(w[r], h, l);
    g_w1h[i] = h; g_w1l[i] = l;
}

// ============ conv1x1 v4: q/k/v in one CTA, chunked-B pipeline ============
// blockIdx.x = y*2 + oh. block 128. smem 104448. 2 CTAs/SM.
__global__ __launch_bounds__(128, 2)
void conv1_v4_kernel()
{
    extern __shared__ __align__(16) char smem[];
    u32 sb = smem_u32(smem);
    const u32 AH = 0, AL = 34816;
    const u32 BUF0 = 69632, BUF1 = 87040;   // 17408 each

    int bx = blockIdx.x, img = blockIdx.y;
    int y = bx >> 1, oh = bx & 1;
    int tid = threadIdx.x, wid = tid >> 5;
    int px0 = wid * 32;

    // prologue: stage A + chunk0 (one group), then chunk1 (second group)
    size_t abase = (((size_t)img * 128 + y) * 128) * 128;
    for (int idx = tid; idx < 2048; idx += 128) {
        int row = idx >> 4, k8 = (idx & 15) << 3;
        u32 d = (u32)(row * 136 + k8) * 2;
        cpa16(sb + AH + d, g_xh + abase + row * 128 + k8);
        cpa16(sb + AL + d, g_xl + abase + row * 128 + k8);
    }
    {
        const __nv_bfloat16* src = g_w1h + oh * 8192;   // chunk0: o=0, hl=0
        for (int idx = tid; idx < 1024; idx += 128) {
            int row = idx >> 4, k8 = (idx & 15) << 3;
            cpa16(sb + BUF0 + (u32)(row * 136 + k8) * 2, src + row * 128 + k8);
        }
        CP_COMMIT();
        src = g_w1l + oh * 8192;                         // chunk1: o=0, hl=1
        for (int idx = tid; idx < 1024; idx += 128) {
            int row = idx >> 4, k8 = (idx & 15) << 3;
            cpa16(sb + BUF1 + (u32)(row * 136 + k8) * 2, src + row * 128 + k8);
        }
        CP_COMMIT();
    }

    FragC acc[2][4];
#pragma unroll
    for (int i = 0; i < 2; i++)
#pragma unroll
        for (int j = 0; j < 4; j++) wmma::fill_fragment(acc[i][j], 0.f);

    const __nv_bfloat16* pAh = (const __nv_bfloat16*)(smem + AH) + px0 * 136;
    const __nv_bfloat16* pAl = (const __nv_bfloat16*)(smem + AL) + px0 * 136;

    for (int c = 0; c < 6; c++) {
        int o = c >> 1, hl = c & 1;
        if (c < 5) { CP_WAIT(1); } else { CP_WAIT(0); }
        __syncthreads();

        const __nv_bfloat16* pB =
            (const __nv_bfloat16*)(smem + ((c & 1) ? BUF1 : BUF0));
        if (hl == 0) mma_bh(pAh, pAl, pB, acc);
        else         mma_bl(pAh, pB, acc);
        __syncthreads();

        if (c + 2 < 6) {
            int c2 = c + 2, o2 = c2 >> 1, hl2 = c2 & 1;
            const __nv_bfloat16* src =
                (hl2 ? g_w1l : g_w1h) + (size_t)o2 * 16384 + oh * 8192;
            u32 buf = (c2 & 1) ? BUF1 : BUF0;
            for (int idx = tid; idx < 1024; idx += 128) {
                int row = idx >> 4, k8 = (idx & 15) << 3;
                cpa16(sb + buf + (u32)(row * 136 + k8) * 2, src + row * 128 + k8);
            }
            CP_COMMIT();
        }

        if (hl == 1) {
            size_t cbase = ((size_t)(o * 16 + img) * 16384 + (size_t)y * 128);
#pragma unroll
            for (int i = 0; i < 2; i++)
#pragma unroll
                for (int j = 0; j < 4; j++) {
                    wmma::store_matrix_sync(
                        g_c1 + (cbase + px0 + 16 * i) * 128 + oh * 64 + 16 * j,
                        acc[i][j], 128, wmma::mem_row_major);
                    wmma::fill_fragment(acc[i][j], 0.f);
                }
        }
    }
}

// ============ qkv scatter: dense -> windowed (+bias, bf16 split for s>=2) ====
__global__ __launch_bounds__(256)
void qkv_scatter_kernel(const float* __restrict__ bq, const float* __restrict__ bk,
                        const float* __restrict__ bv)
{
    extern __shared__ __align__(16) char smemc[];
    float* Cs = (float*)smemc;   // [128][132]
    int y = blockIdx.x, img = blockIdx.y, tid = threadIdx.x;
    int b = img >> 3, t = img & 7;
    int pq = tid & 31, og = tid >> 5;

    for (int o = 0; o < 3; o++) {
        __syncthreads();
        const float* src = g_c1 + ((size_t)(o * 16 + img) * 16384 + (size_t)y * 128) * 128;
        for (int idx = tid; idx < 4096; idx += 256) {
            int px = idx >> 5, oc4 = (idx & 31) * 4;
            *(float4*)&Cs[px * 132 + oc4] = *(const float4*)(src + (size_t)px * 128 + oc4);
        }
        __syncthreads();

        const float* bias = (o == 0) ? bq : (o == 1) ? bk : bv;
        float* dstf = (o == 0) ? g_qw : (o == 1) ? g_kw : g_vw;
        __nv_bfloat16* dsth = (o == 0) ? g_qh : (o == 1) ? g_kh : g_vh;
        __nv_bfloat16* dstl = (o == 0) ? g_ql : (o == 1) ? g_kl : g_vl;

        for (int j = 0; j < 16; j++) {
            int oc = og * 16 + j;
            int s = oc >> 5, lph = 7 - s;
            int phm = (1 << lph) - 1;
            int n_s = 8 << (2 * s), d_s = 524288 >> (2 * s);
            int oy = y >> lph, py = y & phm;
            int tokb = ((t << s) + oy) << s;
            int eb = (((oc & 31) << lph) + py) << lph;
            float bv2 = bias[oc];
            size_t base2 = ((size_t)(b * n_s + tokb)) * d_s + eb;
#pragma unroll
            for (int k2 = 0; k2 < 4; k2++) {
                int px = pq + 32 * k2;
                int ox = px >> lph, pxm = px & phm;
                float v = Cs[px * 132 + oc] + bv2;
                size_t a = base2 + (size_t)ox * d_s + pxm;
                if (s < 2) {
                    dstf[(size_t)s * 8388608 + a] = v;
                } else {
                    __nv_bfloat16 h, l;
                    bsplit(v, h, l);
                    dsth[(size_t)(s - 2) * 8388608 + a] = h;
                    dstl[(size_t)(s - 2) * 8388608 + a] = l;
                }
            }
        }
    }
}

// ============ scale-0 scores (n=8, d=524288, fp32) ============
__global__ __launch_bounds__(256)
void scores0_kernel()
{
    __shared__ float Qs[8][516];
    __shared__ float Ks[8][516];
    __shared__ float sred[256];
    int z = blockIdx.x, b = blockIdx.y, tid = threadIdx.x;
    const int d = 524288;

    const float* qb = g_qw + ((size_t)(b * 8)) * d + z * 512;
    const float* kb = g_kw + ((size_t)(b * 8)) * d + z * 512;
    for (int idx = tid; idx < 1024; idx += 256) {
        int r = idx >> 7, c4 = (idx & 127) * 4;
        *(float4*)&Qs[r][c4] = *(const float4*)(qb + (size_t)r * d + c4);
        *(float4*)&Ks[r][c4] = *(const float4*)(kb + (size_t)r * d + c4);
    }
    __syncthreads();

    int rm = tid & 63, r = rm >> 3, m = rm & 7, kg = tid >> 6;
    ull acc = 0ull;
    int kb0 = kg * 128;
#pragma unroll
    for (int kk2 = 0; kk2 < 64; kk2++)
        ffma2(acc, *(const ull*)&Qs[r][kb0 + 2 * kk2], *(const ull*)&Ks[m][kb0 + 2 * kk2]);
    sred[tid] = hsum2(acc);
    __syncthreads();
    if (tid < 64)
        g_part[(size_t)(z * NBm + b) * 64 + tid] =
            sred[tid] + sred[tid + 64] + sred[tid + 128] + sred[tid + 192];
}

// ============ scale-1 scores (scalar, split-k) ============
template<int BN, int TN>
__global__ __launch_bounds__(256)
void scores2_kernel(int n, int d, long long off_ll, int tilesM, int dchunk)
{
    __shared__ float Qs[BN][68];
    __shared__ float Ks[BN][68];
    size_t off = (size_t)off_ll;
    int b = blockIdx.y, z = blockIdx.z;
    int tn = blockIdx.x / tilesM, tm = blockIdx.x - tn * tilesM;
    int n0 = tn * BN, m0 = tm * BN;
    int tx = threadIdx.x, ty = threadIdx.y, tid = ty * 16 + tx;

    ull acc[TN][TN];
#pragma unroll
    for (int i = 0; i < TN; i++)
#pragma unroll
        for (int j = 0; j < TN; j++) acc[i][j] = 0ull;

    const float* qb = g_qw + off + ((size_t)(b * n + n0)) * d;
    const float* kb = g_kw + off + ((size_t)(b * n + m0)) * d;
    int r0 = ty * TN;
    int k0s = z * dchunk;

    for (int k0 = k0s; k0 < k0s + dchunk; k0 += 64) {
        for (int idx = tid; idx < BN * 16; idx += 256) {
            int r = idx >> 4, c4 = (idx & 15) * 4;
            *(float4*)&Qs[r][c4] = *(const float4*)(qb + (size_t)r * d + k0 + c4);
            *(float4*)&Ks[r][c4] = *(const float4*)(kb + (size_t)r * d + k0 + c4);
        }
        __syncthreads();
#pragma unroll
        for (int kk2 = 0; kk2 < 32; kk2++) {
            ull q2[TN], k2[TN];
#pragma unroll
            for (int i = 0; i < TN; i++) q2[i] = *(const ull*)&Qs[r0 + i][2 * kk2];
#pragma unroll
            for (int j = 0; j < TN; j++) k2[j] = *(const ull*)&Ks[tx + 16 * j][2 * kk2];
#pragma unroll
            for (int i = 0; i < TN; i++)
#pragma unroll
                for (int j = 0; j < TN; j++) ffma2(acc[i][j], q2[i], k2[j]);
        }
        __syncthreads();
    }

    size_t base = ((size_t)(z * NBm + b)) * n * n;
#pragma unroll
    for (int i = 0; i < TN; i++)
#pragma unroll
        for (int j = 0; j < TN; j++)
            g_part[base + (size_t)(n0 + r0 + i) * n + (m0 + tx + 16 * j)] =
                hsum2(acc[i][j]);
}

// ============ WMMA scores (scales 2,3) ============
__global__ __launch_bounds__(256)
void scores_wmma_kernel(int n, int d, long long offb_ll, int tilesM, int dchunk)
{
    extern __shared__ __align__(16) char smem[];
    u32 sb = smem_u32(smem);
    const u32 QH = 0, QL = 34816, KH = 69632, KL = 104448;
    size_t offb = (size_t)offb_ll;
    int b = blockIdx.y, z = blockIdx.z;
    int tn = blockIdx.x / tilesM, tm = blockIdx.x - tn * tilesM;
    int n0 = tn * 128, m0 = tm * 128;
    int tid = threadIdx.x, wid = tid >> 5;
    int px0 = (wid & 3) * 32, oc0 = (wid >> 2) * 64;

    const __nv_bfloat16* qh = g_qh + offb + ((size_t)(b * n + n0)) * d;
    const __nv_bfloat16* ql = g_ql + offb + ((size_t)(b * n + n0)) * d;
    const __nv_bfloat16* kh = g_kh + offb + ((size_t)(b * n + m0)) * d;
    const __nv_bfloat16* kl = g_kl + offb + ((size_t)(b * n + m0)) * d;

    FragC acc[2][4];
#pragma unroll
    for (int i = 0; i < 2; i++)
#pragma unroll
        for (int j = 0; j < 4; j++) wmma::fill_fragment(acc[i][j], 0.f);

    int k0s = z * dchunk;
    for (int k0 = k0s; k0 < k0s + dchunk; k0 += 128) {
        for (int idx = tid; idx < 2048; idx += 256) {
            int r = idx >> 4, k8 = (idx & 15) << 3;
            u32 dd = (u32)(r * 136 + k8) * 2;
            size_t go = (size_t)r * d + k0 + k8;
            cpa16(sb + QH + dd, qh + go);
            cpa16(sb + QL + dd, ql + go);
            cpa16(sb + KH + dd, kh + go);
            cpa16(sb + KL + dd, kl + go);
        }
        CP_COMMIT(); CP_WAIT(0);
        __syncthreads();
        mma3<false, FragB>((const __nv_bfloat16*)(smem + QH) + px0 * 136,
                           (const __nv_bfloat16*)(smem + QL) + px0 * 136,
                           (const __nv_bfloat16*)(smem + KH) + oc0 * 136,
                           (const __nv_bfloat16*)(smem + KL) + oc0 * 136, acc);
        __syncthreads();
    }

    size_t base = ((size_t)(z * NBm + b)) * n * n;
#pragma unroll
    for (int i = 0; i < 2; i++)
#pragma unroll
        for (int j = 0; j < 4; j++)
            wmma::store_matrix_sync(
                g_part + base + (size_t)(n0 + px0 + 16 * i) * n + m0 + oc0 + 16 * j,
                acc[i][j], n, wmma::mem_row_major);
}

// ============ reduce + softmax (+ optional bf16 attn output) ============
__global__ __launch_bounds__(256)
void softmax_kernel(int n, int nsplit, float isd, int wbf)
{
    __shared__ float sbuf[512];
    __shared__ float red[256];
    int row = blockIdx.x, b = blockIdx.y, tid = threadIdx.x;

    if (n <= 32) {
        int m = tid % n, zi = tid / n, tpm = 256 / n;
        float s = 0.f;
        for (int z = zi; z < nsplit; z += tpm)
            s += g_part[((size_t)(z * NBm + b) * n + row) * n + m];
        red[tid] = s;
        __syncthreads();
        if (tid < n) {
            float t = 0.f;
            for (int j = 0; j < tpm; j++) t += red[tid + j * n];
            sbuf[tid] = t * isd;
        }
    } else {
        for (int m = tid; m < n; m += 256) {
            float s = 0.f;
            for (int z = 0; z < nsplit; z++)
                s += g_part[((size_t)(z * NBm + b) * n + row) * n + m];
            sbuf[m] = s * isd;
        }
    }
    __syncthreads();

    float lm = -1e30f;
    for (int m = tid; m < n; m += 256) lm = fmaxf(lm, sbuf[m]);
    red[tid] = lm;
    __syncthreads();
    for (int s = 128; s > 0; s >>= 1) {
        if (tid < s) red[tid] = fmaxf(red[tid], red[tid + s]);
        __syncthreads();
    }
    float mx = red[0];
    __syncthreads();
    float ls = 0.f;
    for (int m = tid; m < n; m += 256) {
        float e = __expf(sbuf[m] - mx);
        sbuf[m] = e; ls += e;
    }
    red[tid] = ls;
    __syncthreads();
    for (int s = 128; s > 0; s >>= 1) {
        if (tid < s) red[tid] += red[tid + s];
        __syncthreads();
    }
    float inv = 1.0f / red[0];
    for (int m = tid; m < n; m += 256) {
        float p = sbuf[m] * inv;
        size_t o = ((size_t)b * n + row) * n + m;
        if (wbf) {
            __nv_bfloat16 h, l;
            bsplit(p, h, l);
            g_ath[o] = h; g_atl[o] = l;
        } else {
            g_attn[o] = p;
        }
    }
}

// ============ scalar AV (scales 0,1) ============
template<int BN, int TN>
__global__ __launch_bounds__(256)
void av2_kernel(int n, int d, long long off_ll)
{
    __shared__ float As[BN][34];
    __shared__ float Vs[32][66];
    size_t off = (size_t)off_ll;
    int b = blockIdx.z, n0 = blockIdx.y * BN, e0 = blockIdx.x * 64;
    int tx = threadIdx.x, ty = threadIdx.y, tid = ty * 16 + tx;

    ull acc[TN][2];
#pragma unroll
    for (int i = 0; i < TN; i++) { acc[i][0] = 0ull; acc[i][1] = 0ull; }
    int r0 = ty * TN;

    const float* vb = g_vw + off + e0;

    for (int m0 = 0; m0 < n; m0 += 32) {
        for (int idx = tid; idx < BN * 8; idx += 256) {
            int r = idx >> 3, c4 = (idx & 7) * 4;
            float4 v = (m0 + c4 < n)
                ? *(const float4*)(g_attn + ((size_t)(b * n + n0 + r)) * n + m0 + c4)
                : make_float4(0.f, 0.f, 0.f, 0.f);
            As[r][c4] = v.x; As[r][c4 + 1] = v.y; As[r][c4 + 2] = v.z; As[r][c4 + 3] = v.w;
        }
        for (int idx = tid; idx < 512; idx += 256) {
            int mm = idx >> 4, e4 = (idx & 15) * 4;
            float4 v = (m0 + mm < n)
                ? *(const float4*)(vb + ((size_t)(b * n + m0 + mm)) * d + e4)
                : make_float4(0.f, 0.f, 0.f, 0.f);
            Vs[mm][e4] = v.x; Vs[mm][e4 + 1] = v.y; Vs[mm][e4 + 2] = v.z; Vs[mm][e4 + 3] = v.w;
        }
        __syncthreads();
#pragma unroll
        for (int kk = 0; kk < 32; kk++) {
            ull v2a = *(const ull*)&Vs[kk][2 * tx];
            ull v2b = *(const ull*)&Vs[kk][2 * tx + 32];
#pragma unroll
            for (int i = 0; i < TN; i++) {
                ull a2 = pack2(As[r0 + i][kk]);
                ffma2(acc[i][0], a2, v2a);
                ffma2(acc[i][1], a2, v2b);
            }
        }
        __syncthreads();
    }

    float* ob = g_ow + off;
#pragma unroll
    for (int i = 0; i < TN; i++) {
        size_t rb = ((size_t)(b * n + n0 + r0 + i)) * d + e0;
        *(float2*)(ob + rb + 2 * tx)      = *reinterpret_cast<float2*>(&acc[i][0]);
        *(float2*)(ob + rb + 2 * tx + 32) = *reinterpret_cast<float2*>(&acc[i][1]);
    }
}

// ============ WMMA AV (scales 2,3) ============
__global__ __launch_bounds__(256)
void av_wmma_kernel(int n, int d, long long offb_ll, long long off32_ll)
{
    extern __shared__ __align__(16) char smem[];
    u32 sb = smem_u32(smem);
    const u32 AH = 0, AL = 34816, VH = 69632, VL = 104448;
    size_t offb = (size_t)offb_ll, off32 = (size_t)off32_ll;
    int b = blockIdx.z, n0 = blockIdx.y * 128, e0 = blockIdx.x * 128;
    int tid = threadIdx.x, wid = tid >> 5;
    int px0 = (wid & 3) * 32, oc0 = (wid >> 2) * 64;

    FragC acc[2][4];
#pragma unroll
    for (int i = 0; i < 2; i++)
#pragma unroll
        for (int j = 0; j < 4; j++) wmma::fill_fragment(acc[i][j], 0.f);

    for (int m0 = 0; m0 < n; m0 += 128) {
        for (int idx = tid; idx < 2048; idx += 256) {
            int r = idx >> 4, k8 = (idx & 15) << 3;
            u32 dd = (u32)(r * 136 + k8) * 2;
            size_t ao = ((size_t)(b * n + n0 + r)) * n + m0 + k8;
            size_t vo = offb + ((size_t)(b * n + m0 + r)) * d + e0 + k8;
            cpa16(sb + AH + dd, g_ath + ao);
            cpa16(sb + AL + dd, g_atl + ao);
            cpa16(sb + VH + dd, g_vh + vo);
            cpa16(sb + VL + dd, g_vl + vo);
        }
        CP_COMMIT(); CP_WAIT(0);
        __syncthreads();
        mma3<true, FragBr>((const __nv_bfloat16*)(smem + AH) + px0 * 136,
                           (const __nv_bfloat16*)(smem + AL) + px0 * 136,
                           (const __nv_bfloat16*)(smem + VH) + oc0,
                           (const __nv_bfloat16*)(smem + VL) + oc0, acc);
        __syncthreads();
    }

#pragma unroll
    for (int i = 0; i < 2; i++)
#pragma unroll
        for (int j = 0; j < 4; j++)
            wmma::store_matrix_sync(
                g_ow + off32 + ((size_t)(b * n + n0 + px0 + 16 * i)) * d + e0 + oc0 + 16 * j,
                acc[i][j], d, wmma::mem_row_major);
}

// ============ unpack windowed -> channel-last bf16 hi/lo ============
__global__ __launch_bounds__(256)
void unpack2_kernel()
{
    __shared__ float sbm[64][130];
    int y = blockIdx.x, img = blockIdx.y, tid = threadIdx.x;
    int b = img >> 3, t = img & 7;
    for (int ch = 0; ch < 2; ch++) {
        for (int idx = tid; idx < 64 * 128; idx += 256) {
            int cl = idx >> 7, xp = idx & 127;
            int c = ch * 64 + cl;
            int s = c >> 5, lph = 7 - s;
            int phm = (1 << lph) - 1;
            int n_s = 8 << (2 * s), d_s = 524288 >> (2 * s);
            int oy = y >> lph, py = y & phm;
            int ox = xp >> lph, pxm = xp & phm;
            int tok = ((((t << s) + oy) << s) + ox);
            int e = ((((c & 31) << lph) + py) << lph) + pxm;
            sbm[cl][xp] = g_ow[(size_t)s * 8388608 + ((size_t)(b * n_s + tok)) * d_s + e];
        }
        __syncthreads();
        for (int idx = tid; idx < 64 * 128; idx += 256) {
            int px = idx >> 6, cl = idx & 63;
            __nv_bfloat16 h, l;
            bsplit(sbm[cl][px], h, l);
            size_t o = (((size_t)img * 128 + y) * 128 + px) * 128 + ch * 64 + cl;
            g_ah[o] = h; g_al[o] = l;
        }
        __syncthreads();
    }
}

// ============ conv3x3 v4: chunked-B pipeline, 2 CTAs/SM ============
// blockIdx.x = y*2 + oh. block 128. smem 107584.
__global__ __launch_bounds__(128, 2)
void conv3_v4_kernel(const float* __restrict__ bias, float* __restrict__ out)
{
    extern __shared__ __align__(16) char smem[];
    u32 sb = smem_u32(smem);
    const u32 AH = 0, AL = 35360;
    const u32 BUF0 = 70720, BUF1 = 88128;   // 17408 each

    int bx = blockIdx.x, img = blockIdx.y;
    int y = bx >> 1, oh = bx & 1;
    int tid = threadIdx.x, wid = tid >> 5;
    int px0 = wid * 32;

    FragC acc[2][4];
#pragma unroll
    for (int i = 0; i < 2; i++)
#pragma unroll
        for (int j = 0; j < 4; j++) wmma::fill_fragment(acc[i][j], 0.f);

    // prologue: chunk0, chunk1 (tap 0 hi/lo)
    {
        const __nv_bfloat16* src = g_w3h + oh * 8192;
        for (int idx = tid; idx < 1024; idx += 128) {
            int row = idx >> 4, k8 = (idx & 15) << 3;
            cpa16(sb + BUF0 + (u32)(row * 136 + k8) * 2, src + row * 128 + k8);
        }
        CP_COMMIT();
        src = g_w3l + oh * 8192;
        for (int idx = tid; idx < 1024; idx += 128) {
            int row = idx >> 4, k8 = (idx & 15) << 3;
            cpa16(sb + BUF1 + (u32)(row * 136 + k8) * 2, src + row * 128 + k8);
        }
        CP_COMMIT();
    }

    for (int c = 0; c < 18; c++) {
        int tap = c >> 1, hl = c & 1;
        int ky = tap / 3, kx = tap - ky * 3;

        if ((c % 6) == 0) {
            // new ky: stage A synchronously (prior MMA consumers must be done)
            __syncthreads();
            int yy = y + ky - 1;
            bool yok = (yy >= 0 && yy < 128);
            size_t abase = (((size_t)img * 128 + (yok ? yy : 0)) * 128) * 128;
            for (int idx = tid; idx < 2080; idx += 128) {
                int i = idx >> 4, k8 = (idx & 15) << 3;
                int px = i - 1;
                u32 d = (u32)(i * 136 + k8) * 2;
                if (yok && px >= 0 && px < 128) {
                    size_t o = abase + (size_t)px * 128 + k8;
                    cpa16(sb + AH + d, g_ah + o);
                    cpa16(sb + AL + d, g_al + o);
                } else {
                    uint4 zz = make_uint4(0, 0, 0, 0);
                    *(uint4*)(smem + AH + d) = zz;
                    *(uint4*)(smem + AL + d) = zz;
                }
            }
            CP_COMMIT();
            CP_WAIT(0);
        } else if (c == 17) {
            CP_WAIT(0);
        } else {
            CP_WAIT(1);
        }
        __syncthreads();

        const __nv_bfloat16* pAh =
            (const __nv_bfloat16*)(smem + AH) + (px0 + kx) * 136;
        const __nv_bfloat16* pAl =
            (const __nv_bfloat16*)(smem + AL) + (px0 + kx) * 136;
        const __nv_bfloat16* pB =
            (const __nv_bfloat16*)(smem + ((c & 1) ? BUF1 : BUF0));
        if (hl == 0) mma_bh(pAh, pAl, pB, acc);
        else         mma_bl(pAh, pB, acc);
        __syncthreads();

        if (c + 2 < 18) {
            int c2 = c + 2, tap2 = c2 >> 1, hl2 = c2 & 1;
            const __nv_bfloat16* src =
                (hl2 ? g_w3l : g_w3h) + (size_t)tap2 * 16384 + oh * 8192;
            u32 buf = (c2 & 1) ? BUF1 : BUF0;
            for (int idx = tid; idx < 1024; idx += 128) {
                int row = idx >> 4, k8 = (idx & 15) << 3;
                cpa16(sb + buf + (u32)(row * 136 + k8) * 2, src + row * 128 + k8);
            }
            CP_COMMIT();
        }
    }
    __syncthreads();

    float* Cs = (float*)(smem + BUF0);    // [128][72]
#pragma unroll
    for (int i = 0; i < 2; i++)
#pragma unroll
        for (int j = 0; j < 4; j++)
            wmma::store_matrix_sync(&Cs[(px0 + 16 * i) * 72 + 16 * j],
                                    acc[i][j], 72, wmma::mem_row_major);
    __syncthreads();

    for (int idx = tid; idx < 8192; idx += 128) {
        int oc = idx >> 7, px = idx & 127;
        float v = Cs[px * 72 + oc] + bias[oh * 64 + oc];
        out[((size_t)img * 128 + oh * 64 + oc) * HWs + (size_t)y * 128 + px] =
            fmaxf(v, 0.f);
    }
}

// ============ launch ============
extern "C" void kernel_launch(void* const* d_in, const int* in_sizes, int n_in,
                              void* d_out, int out_size)
{
    const float* x  = (const float*)d_in[0];
    const float* wq = (const float*)d_in[1];
    const float* bq = (const float*)d_in[2];
    const float* wk = (const float*)d_in[3];
    const float* bk = (const float*)d_in[4];
    const float* wv = (const float*)d_in[5];
    const float* bv = (const float*)d_in[6];
    const float* wo = (const float*)d_in[7];
    const float* bo = (const float*)d_in[8];
    float* out = (float*)d_out;

    const int smem1 = 104448, smem3 = 107584, smemW = 139264, smemS = 67584;
    cudaFuncSetAttribute(conv1_v4_kernel,
                         cudaFuncAttributeMaxDynamicSharedMemorySize, smem1);
    cudaFuncSetAttribute(conv3_v4_kernel,
                         cudaFuncAttributeMaxDynamicSharedMemorySize, smem3);
    cudaFuncSetAttribute(scores_wmma_kernel,
                         cudaFuncAttributeMaxDynamicSharedMemorySize, smemW);
    cudaFuncSetAttribute(av_wmma_kernel,
                         cudaFuncAttributeMaxDynamicSharedMemorySize, smemW);
    cudaFuncSetAttribute(qkv_scatter_kernel,
                         cudaFuncAttributeMaxDynamicSharedMemorySize, smemS);

    dim3 blk(16, 16);

    prep_w3_kernel<<<(9 * 128 * 128 + 255) / 256, 256>>>(wo);
    prep_w1_kernel<<<(3 * 16384 + 255) / 256, 256>>>(wq, wk, wv);
    prep_x_kernel<<<dim3(Hd, BT), 256>>>(x);
    conv1_v4_kernel<<<dim3(256, BT), 128, smem1>>>();
    qkv_scatter_kernel<<<dim3(Hd, BT), 256, smemS>>>(bq, bk, bv);

    // scale 0: n=8, d=524288 (scalar fp32)
    {
        float isd = 1.0f / sqrtf(524288.f);
        scores0_kernel<<<dim3(1024, NBm), 256>>>();
        softmax_kernel<<<dim3(8, NBm), 256>>>(8, 1024, isd, 0);
        av2_kernel<8, 1><<<dim3(524288 / 64, 1, NBm), blk>>>(8, 524288, 0LL);
    }
    // scale 1: n=32, d=131072 (scalar fp32)
    {
        float isd = 1.0f / sqrtf(131072.f);
        scores2_kernel<32, 2><<<dim3(1, NBm, 256), blk>>>(32, 131072, 8388608LL, 1, 512);
        softmax_kernel<<<dim3(32, NBm), 256>>>(32, 256, isd, 0);
        av2_kernel<32, 2><<<dim3(131072 / 64, 1, NBm), blk>>>(32, 131072, 8388608LL);
    }
    // scale 2: n=128, d=32768 (WMMA)
    {
        float isd = 1.0f / sqrtf(32768.f);
        scores_wmma_kernel<<<dim3(1, NBm, 128), 256, smemW>>>(128, 32768, 0LL, 1, 256);
        softmax_kernel<<<dim3(128, NBm), 256>>>(128, 128, isd, 1);
        av_wmma_kernel<<<dim3(256, 1, NBm), 256, smemW>>>(128, 32768, 0LL, 2LL * 8388608);
    }
    // scale 3: n=512, d=8192 (WMMA)
    {
        float isd = 1.0f / sqrtf(8192.f);
        scores_wmma_kernel<<<dim3(16, NBm, 8), 256, smemW>>>(512, 8192, 8388608LL, 4, 1024);
        softmax_kernel<<<dim3(512, NBm), 256>>>(512, 8, isd, 1);
        av_wmma_kernel<<<dim3(64, 4, NBm), 256, smemW>>>(512, 8192, 8388608LL, 3LL * 8388608);
    }

    unpack2_kernel<<<dim3(Hd, BT), 256>>>();
    conv3_v4_kernel<<<dim3(256, BT), 128, smem3>>>(bo, out);

    (void)in_sizes; (void)n_in; (void)out_size;
}